// round 3
// baseline (speedup 1.0000x reference)
#include <cuda_runtime.h>
#include <cuda_bf16.h>

// CorrentropyLoss: cost = mean(1 - exp(-sigma * (2*(output-target))^2))
// shape (65536, 1000), sigma = 1/1000  ->  arg = 0.004 * diff^2
//
// HBM-bound streaming reduction:
//   kernel 1: grid-stride float4 loads (streaming .cs hint, 2x unroll),
//             fp32 accumulation, warp+block reduce, partial -> __device__ array
//   kernel 2: deterministic final reduce of partials, scale by 1/N -> d_out[0]

#define RED_BLOCKS 1184   // 148 SMs * 8 blocks
#define RED_THREADS 256

__device__ float g_partials[RED_BLOCKS];

__device__ __forceinline__ float corr4(float4 a, float4 b) {
    const float C = 0.004f;  // 4 * sigma, sigma = 1/1000
    float d0 = a.x - b.x;
    float d1 = a.y - b.y;
    float d2 = a.z - b.z;
    float d3 = a.w - b.w;
    float s;
    s  = 1.0f - __expf(-C * d0 * d0);
    s += 1.0f - __expf(-C * d1 * d1);
    s += 1.0f - __expf(-C * d2 * d2);
    s += 1.0f - __expf(-C * d3 * d3);
    return s;
}

__global__ __launch_bounds__(RED_THREADS)
void corr_partial_kernel(const float4* __restrict__ o,
                         const float4* __restrict__ t,
                         int n4)
{
    float acc = 0.0f;

    int stride = gridDim.x * blockDim.x;
    int i = blockIdx.x * blockDim.x + threadIdx.x;

    // 2x unrolled main loop: 4 independent 16B loads in flight per iter
    for (; i + stride < n4; i += 2 * stride) {
        float4 a0 = __ldcs(&o[i]);
        float4 b0 = __ldcs(&t[i]);
        float4 a1 = __ldcs(&o[i + stride]);
        float4 b1 = __ldcs(&t[i + stride]);
        acc += corr4(a0, b0);
        acc += corr4(a1, b1);
    }
    if (i < n4) {
        float4 a = __ldcs(&o[i]);
        float4 b = __ldcs(&t[i]);
        acc += corr4(a, b);
    }

    // warp reduce
    #pragma unroll
    for (int off = 16; off > 0; off >>= 1)
        acc += __shfl_xor_sync(0xffffffffu, acc, off);

    __shared__ float smem[RED_THREADS / 32];
    int lane = threadIdx.x & 31;
    int wid  = threadIdx.x >> 5;
    if (lane == 0) smem[wid] = acc;
    __syncthreads();

    if (threadIdx.x == 0) {
        float s = 0.0f;
        #pragma unroll
        for (int w = 0; w < RED_THREADS / 32; w++) s += smem[w];
        g_partials[blockIdx.x] = s;
    }
}

__global__ __launch_bounds__(1024)
void corr_final_kernel(float* __restrict__ out, float inv_n)
{
    float acc = 0.0f;
    for (int i = threadIdx.x; i < RED_BLOCKS; i += blockDim.x)
        acc += g_partials[i];

    #pragma unroll
    for (int off = 16; off > 0; off >>= 1)
        acc += __shfl_xor_sync(0xffffffffu, acc, off);

    __shared__ float smem[32];
    int lane = threadIdx.x & 31;
    int wid  = threadIdx.x >> 5;
    if (lane == 0) smem[wid] = acc;
    __syncthreads();

    if (threadIdx.x == 0) {
        float s = 0.0f;
        #pragma unroll
        for (int w = 0; w < 32; w++) s += smem[w];
        out[0] = s * inv_n;
    }
}

extern "C" void kernel_launch(void* const* d_in, const int* in_sizes, int n_in,
                              void* d_out, int out_size)
{
    const float4* o = (const float4*)d_in[0];
    const float4* t = (const float4*)d_in[1];
    float* out = (float*)d_out;

    int n = in_sizes[0];        // 65,536,000 elements, divisible by 4
    int n4 = n >> 2;
    float inv_n = 1.0f / (float)n;

    corr_partial_kernel<<<RED_BLOCKS, RED_THREADS>>>(o, t, n4);
    corr_final_kernel<<<1, 1024>>>(out, inv_n);
}